// round 7
// baseline (speedup 1.0000x reference)
#include <cuda_runtime.h>

// ---------------------------------------------------------------------------
// TreeLSTM over complete binary tree, depth 18, N = 2^18-1 = 262143 nodes.
// V=32000, X=H=128, C=5.
//
// Plan:
//   Phase A : x_all[N][512] = emb_table[x_ids*mask] @ [W_iou(384) | W_f(128)] + bias
//   leaves  : elementwise LSTM cell (fc = 0), writes h, c, and fused out-proj
//   d=16..0 : GEMM1  t_iou[n][384] = (h_L + h_R) @ U_iou     (child-sum in A-load)
//             GEMM2  t_f[2n][128]  = h_child @ U_f
//             elementwise cell + fused out = h @ W_out + b_out
//
// GEMM: 128x128 block tile, BK=16, 256 threads, 8x8 per thread, double-buffered
// smem, packed fma.rn.f32x2 accumulation (2 FMA per issue slot on sm_103a).
// ---------------------------------------------------------------------------

#define NTOT 262143

// Scratch (device globals: allocation inside kernel_launch is forbidden)
__device__ float g_xall[(size_t)NTOT * 512];   // [iou(384) | x_f(128)]
__device__ float g_h[(size_t)NTOT * 128];
__device__ float g_c[(size_t)NTOT * 128];
__device__ float g_tiou[(size_t)65536 * 384];  // per-level U_iou output (max level 16)
__device__ float g_tf[(size_t)131072 * 128];   // per-level U_f output (max children)

// ---------------------------------------------------------------------------
// Generic 128x128x128 GEMM.  MODE 0: A = gathered embeddings (row g).
//                            MODE 1: A[r] = h[base1+2r] + h[base1+2r+1].
//                            MODE 2: A[r] = h[base1+r].
// C[r*ldc + colOff + blockIdx.y*128 + col] = A @ Bmat(+bias)
// ---------------------------------------------------------------------------
template <int MODE>
__global__ void __launch_bounds__(256)
gemm128(const int M,
        const float* __restrict__ Bmat, const int ldb,
        const float* __restrict__ bias,
        float* __restrict__ C, const int ldc, const int colOff,
        const int* __restrict__ x_ids, const int* __restrict__ mask,
        const float* __restrict__ emb,
        const float* __restrict__ hbuf, const long base1)
{
    __shared__ __align__(16) float As[2][16][128];
    __shared__ __align__(16) float Bs[2][16][128];

    const int tid = threadIdx.x;
    const int tx = tid & 15;       // 16 col-groups of 8
    const int ty = tid >> 4;       // 16 row-groups of 8

    const int aRow = tid >> 2;           // 0..63 (and +64)
    const int aK   = (tid & 3) << 2;     // 0,4,8,12
    const int bK   = tid >> 5;           // 0..7 (and +8)
    const int bCol = (tid & 31) << 2;    // 0..124

    const long rowBase  = (long)blockIdx.x * 128;
    const int  colBlock = blockIdx.y * 128;

    long r0 = rowBase + aRow;      if (r0 > (long)M - 1) r0 = M - 1;
    long r1 = rowBase + aRow + 64; if (r1 > (long)M - 1) r1 = M - 1;

    const float *pA0, *pA1, *pA0b = nullptr, *pA1b = nullptr;
    if (MODE == 0) {
        pA0 = emb + (long)(x_ids[r0] * mask[r0]) * 128;
        pA1 = emb + (long)(x_ids[r1] * mask[r1]) * 128;
    } else if (MODE == 1) {
        pA0  = hbuf + (base1 + 2 * r0) * 128;  pA0b = pA0 + 128;
        pA1  = hbuf + (base1 + 2 * r1) * 128;  pA1b = pA1 + 128;
    } else {
        pA0 = hbuf + (base1 + r0) * 128;
        pA1 = hbuf + (base1 + r1) * 128;
    }

    const float* pB0 = Bmat + (long)bK * ldb + colBlock + bCol;
    const float* pB1 = Bmat + (long)(bK + 8) * ldb + colBlock + bCol;

    float4 a0, a1, b0, b1;

    auto loadTile = [&](int kt) {
        a0 = *(const float4*)(pA0 + kt + aK);
        a1 = *(const float4*)(pA1 + kt + aK);
        if (MODE == 1) {
            float4 t0 = *(const float4*)(pA0b + kt + aK);
            float4 t1 = *(const float4*)(pA1b + kt + aK);
            a0.x += t0.x; a0.y += t0.y; a0.z += t0.z; a0.w += t0.w;
            a1.x += t1.x; a1.y += t1.y; a1.z += t1.z; a1.w += t1.w;
        }
        b0 = *(const float4*)(pB0 + (long)kt * ldb);
        b1 = *(const float4*)(pB1 + (long)kt * ldb);
    };
    auto stage = [&](int buf) {
        As[buf][aK + 0][aRow] = a0.x;
        As[buf][aK + 1][aRow] = a0.y;
        As[buf][aK + 2][aRow] = a0.z;
        As[buf][aK + 3][aRow] = a0.w;
        As[buf][aK + 0][aRow + 64] = a1.x;
        As[buf][aK + 1][aRow + 64] = a1.y;
        As[buf][aK + 2][aRow + 64] = a1.z;
        As[buf][aK + 3][aRow + 64] = a1.w;
        *(float4*)&Bs[buf][bK][bCol]     = b0;
        *(float4*)&Bs[buf][bK + 8][bCol] = b1;
    };

    loadTile(0);
    stage(0);
    __syncthreads();

    // packed f32x2 accumulators: acc2[i][j] holds cols {2j, 2j+1} of row i
    unsigned long long acc2[8][4];
    #pragma unroll
    for (int i = 0; i < 8; ++i)
        #pragma unroll
        for (int j = 0; j < 4; ++j) acc2[i][j] = 0ull;

    #pragma unroll
    for (int t = 0; t < 8; ++t) {
        const int cur = t & 1;
        if (t < 7) loadTile((t + 1) * 16);

        #pragma unroll
        for (int kk = 0; kk < 16; ++kk) {
            float av[8];
            *(float4*)&av[0] = *(const float4*)&As[cur][kk][ty * 8];
            *(float4*)&av[4] = *(const float4*)&As[cur][kk][ty * 8 + 4];
            ulonglong2 q0 = *(const ulonglong2*)&Bs[cur][kk][tx * 8];
            ulonglong2 q1 = *(const ulonglong2*)&Bs[cur][kk][tx * 8 + 4];
            unsigned long long bv2[4] = {q0.x, q0.y, q1.x, q1.y};
            #pragma unroll
            for (int i = 0; i < 8; ++i) {
                unsigned long long aD;
                asm("mov.b64 %0, {%1, %1};" : "=l"(aD) : "r"(__float_as_uint(av[i])));
                #pragma unroll
                for (int j = 0; j < 4; ++j)
                    asm("fma.rn.f32x2 %0, %1, %2, %0;"
                        : "+l"(acc2[i][j]) : "l"(aD), "l"(bv2[j]));
            }
        }
        if (t < 7) {
            stage(cur ^ 1);
            __syncthreads();
        }
    }

    float bb[8] = {0.f, 0.f, 0.f, 0.f, 0.f, 0.f, 0.f, 0.f};
    if (bias) {
        #pragma unroll
        for (int j = 0; j < 8; ++j) bb[j] = bias[colBlock + tx * 8 + j];
    }

    const long mBase = rowBase + ty * 8;
    float* Cb = C + colOff + colBlock + tx * 8;
    #pragma unroll
    for (int i = 0; i < 8; ++i) {
        const long r = mBase + i;
        if (r < M) {
            float cv[8];
            #pragma unroll
            for (int j = 0; j < 4; ++j) {
                unsigned int lo, hi;
                asm("mov.b64 {%0, %1}, %2;" : "=r"(lo), "=r"(hi) : "l"(acc2[i][j]));
                cv[2 * j]     = __uint_as_float(lo) + bb[2 * j];
                cv[2 * j + 1] = __uint_as_float(hi) + bb[2 * j + 1];
            }
            *(float4*)(Cb + r * ldc)     = make_float4(cv[0], cv[1], cv[2], cv[3]);
            *(float4*)(Cb + r * ldc + 4) = make_float4(cv[4], cv[5], cv[6], cv[7]);
        }
    }
}

// ---------------------------------------------------------------------------
// Elementwise LSTM cell per level + fused output projection (warp per node).
// ---------------------------------------------------------------------------
__device__ __forceinline__ float sigm(float x) { return 1.0f / (1.0f + __expf(-x)); }

__global__ void __launch_bounds__(256)
node_update(const int n, const long s0, const int internal,
            const float* __restrict__ xall,
            const float* __restrict__ tiou,
            const float* __restrict__ tf,
            float* __restrict__ hbuf, float* __restrict__ cbuf,
            const float* __restrict__ Wout,
            const float* __restrict__ bout,
            float* __restrict__ out)
{
    __shared__ float sW[640];
    __shared__ float sB[5];
    const int tid = threadIdx.x;
    for (int i = tid; i < 640; i += 256) sW[i] = Wout[i];
    if (tid < 5) sB[tid] = bout[tid];
    __syncthreads();

    const int lane = tid & 31;
    const long j = (long)blockIdx.x * 8 + (tid >> 5);
    if (j >= n) return;
    const long g = s0 + j;
    const int k0 = lane * 4;

    const float* xr = xall + g * 512 + k0;
    float4 vi = *(const float4*)(xr);
    float4 vo = *(const float4*)(xr + 128);
    float4 vu = *(const float4*)(xr + 256);
    float4 fc = make_float4(0.f, 0.f, 0.f, 0.f);

    if (internal) {
        const float* ti = tiou + j * 384 + k0;
        float4 d0 = *(const float4*)(ti);
        float4 d1 = *(const float4*)(ti + 128);
        float4 d2 = *(const float4*)(ti + 256);
        vi.x += d0.x; vi.y += d0.y; vi.z += d0.z; vi.w += d0.w;
        vo.x += d1.x; vo.y += d1.y; vo.z += d1.z; vo.w += d1.w;
        vu.x += d2.x; vu.y += d2.y; vu.z += d2.z; vu.w += d2.w;

        float4 xf = *(const float4*)(xr + 384);
        const float* tl = tf + (j * 2) * 128 + k0;
        float4 fl = *(const float4*)(tl);
        float4 fr = *(const float4*)(tl + 128);
        const float* cl = cbuf + (2 * g + 1) * 128 + k0;
        float4 cL = *(const float4*)(cl);
        float4 cR = *(const float4*)(cl + 128);

        fc.x = sigm(xf.x + fl.x) * cL.x + sigm(xf.x + fr.x) * cR.x;
        fc.y = sigm(xf.y + fl.y) * cL.y + sigm(xf.y + fr.y) * cR.y;
        fc.z = sigm(xf.z + fl.z) * cL.z + sigm(xf.z + fr.z) * cR.z;
        fc.w = sigm(xf.w + fl.w) * cL.w + sigm(xf.w + fr.w) * cR.w;
    }

    float4 cc, hh;
    cc.x = sigm(vi.x) * tanhf(vu.x) + fc.x;
    cc.y = sigm(vi.y) * tanhf(vu.y) + fc.y;
    cc.z = sigm(vi.z) * tanhf(vu.z) + fc.z;
    cc.w = sigm(vi.w) * tanhf(vu.w) + fc.w;
    hh.x = sigm(vo.x) * tanhf(cc.x);
    hh.y = sigm(vo.y) * tanhf(cc.y);
    hh.z = sigm(vo.z) * tanhf(cc.z);
    hh.w = sigm(vo.w) * tanhf(cc.w);

    *(float4*)(cbuf + g * 128 + k0) = cc;
    *(float4*)(hbuf + g * 128 + k0) = hh;

    // fused output projection: out[g] = h[g] @ W_out + b_out
    const float* w = sW + k0 * 5;
    float a0 = hh.x * w[0]  + hh.y * w[5]  + hh.z * w[10] + hh.w * w[15];
    float a1 = hh.x * w[1]  + hh.y * w[6]  + hh.z * w[11] + hh.w * w[16];
    float a2 = hh.x * w[2]  + hh.y * w[7]  + hh.z * w[12] + hh.w * w[17];
    float a3 = hh.x * w[3]  + hh.y * w[8]  + hh.z * w[13] + hh.w * w[18];
    float a4 = hh.x * w[4]  + hh.y * w[9]  + hh.z * w[14] + hh.w * w[19];

    #pragma unroll
    for (int off = 16; off > 0; off >>= 1) {
        a0 += __shfl_down_sync(0xffffffffu, a0, off);
        a1 += __shfl_down_sync(0xffffffffu, a1, off);
        a2 += __shfl_down_sync(0xffffffffu, a2, off);
        a3 += __shfl_down_sync(0xffffffffu, a3, off);
        a4 += __shfl_down_sync(0xffffffffu, a4, off);
    }
    if (lane == 0) {
        float* op = out + g * 5;
        op[0] = a0 + sB[0];
        op[1] = a1 + sB[1];
        op[2] = a2 + sB[2];
        op[3] = a3 + sB[3];
        op[4] = a4 + sB[4];
    }
}

// ---------------------------------------------------------------------------
extern "C" void kernel_launch(void* const* d_in, const int* in_sizes, int n_in,
                              void* d_out, int out_size)
{
    const int*   x_ids = (const int*)  d_in[0];
    const int*   mask  = (const int*)  d_in[1];
    const float* emb   = (const float*)d_in[2];
    const float* W_iou = (const float*)d_in[3];
    const float* U_iou = (const float*)d_in[4];
    const float* b_iou = (const float*)d_in[5];
    const float* W_f   = (const float*)d_in[6];
    const float* U_f   = (const float*)d_in[7];
    const float* b_f   = (const float*)d_in[8];
    const float* W_out = (const float*)d_in[9];
    const float* b_out = (const float*)d_in[10];
    float* out = (float*)d_out;

    float *xall, *hb, *cb, *tiou, *tfb;
    cudaGetSymbolAddress((void**)&xall, g_xall);
    cudaGetSymbolAddress((void**)&hb,   g_h);
    cudaGetSymbolAddress((void**)&cb,   g_c);
    cudaGetSymbolAddress((void**)&tiou, g_tiou);
    cudaGetSymbolAddress((void**)&tfb,  g_tf);

    const int T = 256;
    const int MB = (NTOT + 127) / 128;   // 2048

    // Phase A: x_all = gather(emb) @ [W_iou | W_f] + [b_iou | b_f]
    gemm128<0><<<dim3(MB, 3), T>>>(NTOT, W_iou, 384, b_iou, xall, 512, 0,
                                   x_ids, mask, emb, nullptr, 0L);
    gemm128<0><<<dim3(MB, 1), T>>>(NTOT, W_f, 128, b_f, xall, 512, 384,
                                   x_ids, mask, emb, nullptr, 0L);

    // Leaf level: d = 17, n = 131072, s0 = 131071, fc = 0
    node_update<<<131072 / 8, T>>>(131072, 131071L, 0, xall, nullptr, nullptr,
                                   hb, cb, W_out, b_out, out);

    // Internal levels, bottom-up
    for (int d = 16; d >= 0; --d) {
        const int  n   = 1 << d;
        const long s0  = (long)n - 1;
        const long cs0 = 2L * n - 1;   // first child's global index

        gemm128<1><<<dim3((n + 127) / 128, 3), T>>>(
            n, U_iou, 384, nullptr, tiou, 384, 0,
            nullptr, nullptr, nullptr, hb, cs0);

        gemm128<2><<<dim3((2 * n + 127) / 128, 1), T>>>(
            2 * n, U_f, 128, nullptr, tfb, 128, 0,
            nullptr, nullptr, nullptr, hb, cs0);

        node_update<<<(n + 7) / 8, T>>>(n, s0, 1, xall, tiou, tfb,
                                        hb, cb, W_out, b_out, out);
    }
}

// round 10
// speedup vs baseline: 1.0032x; 1.0032x over previous
#include <cuda_runtime.h>

// ---------------------------------------------------------------------------
// TreeLSTM over complete binary tree, depth 18, N = 2^18-1 = 262143 nodes.
// V=32000, X=H=128, C=5.
//
// Plan:
//   Phase A : x_all[N][512] = emb_table[x_ids*mask] @ [W_iou(384) | W_f(128)] + bias
//   leaves  : elementwise LSTM cell (fc = 0), writes h, c, and fused out-proj
//   d=16..0 : GEMM1  t_iou[n][384] = (h_L + h_R) @ U_iou     (child-sum in A-load)
//             GEMM2  t_f[2n][128]  = h_child @ U_f
//             elementwise cell + fused out = h @ W_out + b_out
//
// GEMM: 128x128 block tile, BK=16, 256 threads, 8x8 per thread, double-buffered
// smem, packed fma.rn.f32x2 accumulation (2 FMA per issue slot on sm_103a).
// ---------------------------------------------------------------------------

#define NTOT 262143

// Scratch (device globals: allocation inside kernel_launch is forbidden)
__device__ float g_xall[(size_t)NTOT * 512];   // [iou(384) | x_f(128)]
__device__ float g_h[(size_t)NTOT * 128];
__device__ float g_c[(size_t)NTOT * 128];
__device__ float g_tiou[(size_t)65536 * 384];  // per-level U_iou output (max level 16)
__device__ float g_tf[(size_t)131072 * 128];   // per-level U_f output (max children)

// ---------------------------------------------------------------------------
// Generic 128x128x128 GEMM.  MODE 0: A = gathered embeddings (row g).
//                            MODE 1: A[r] = h[base1+2r] + h[base1+2r+1].
//                            MODE 2: A[r] = h[base1+r].
// C[r*ldc + colOff + blockIdx.y*128 + col] = A @ Bmat(+bias)
// ---------------------------------------------------------------------------
template <int MODE>
__global__ void __launch_bounds__(256)
gemm128(const int M,
        const float* __restrict__ Bmat, const int ldb,
        const float* __restrict__ bias,
        float* __restrict__ C, const int ldc, const int colOff,
        const int* __restrict__ x_ids, const int* __restrict__ mask,
        const float* __restrict__ emb,
        const float* __restrict__ hbuf, const long base1)
{
    __shared__ __align__(16) float As[2][16][128];
    __shared__ __align__(16) float Bs[2][16][128];

    const int tid = threadIdx.x;
    const int tx = tid & 15;       // 16 col-groups of 8
    const int ty = tid >> 4;       // 16 row-groups of 8

    const int aRow = tid >> 2;           // 0..63 (and +64)
    const int aK   = (tid & 3) << 2;     // 0,4,8,12
    const int bK   = tid >> 5;           // 0..7 (and +8)
    const int bCol = (tid & 31) << 2;    // 0..124

    const long rowBase  = (long)blockIdx.x * 128;
    const int  colBlock = blockIdx.y * 128;

    long r0 = rowBase + aRow;      if (r0 > (long)M - 1) r0 = M - 1;
    long r1 = rowBase + aRow + 64; if (r1 > (long)M - 1) r1 = M - 1;

    const float *pA0, *pA1, *pA0b = nullptr, *pA1b = nullptr;
    if (MODE == 0) {
        pA0 = emb + (long)(x_ids[r0] * mask[r0]) * 128;
        pA1 = emb + (long)(x_ids[r1] * mask[r1]) * 128;
    } else if (MODE == 1) {
        pA0  = hbuf + (base1 + 2 * r0) * 128;  pA0b = pA0 + 128;
        pA1  = hbuf + (base1 + 2 * r1) * 128;  pA1b = pA1 + 128;
    } else {
        pA0 = hbuf + (base1 + r0) * 128;
        pA1 = hbuf + (base1 + r1) * 128;
    }

    const float* pB0 = Bmat + (long)bK * ldb + colBlock + bCol;
    const float* pB1 = Bmat + (long)(bK + 8) * ldb + colBlock + bCol;

    float4 a0, a1, b0, b1;

    auto loadTile = [&](int kt) {
        a0 = *(const float4*)(pA0 + kt + aK);
        a1 = *(const float4*)(pA1 + kt + aK);
        if (MODE == 1) {
            float4 t0 = *(const float4*)(pA0b + kt + aK);
            float4 t1 = *(const float4*)(pA1b + kt + aK);
            a0.x += t0.x; a0.y += t0.y; a0.z += t0.z; a0.w += t0.w;
            a1.x += t1.x; a1.y += t1.y; a1.z += t1.z; a1.w += t1.w;
        }
        b0 = *(const float4*)(pB0 + (long)kt * ldb);
        b1 = *(const float4*)(pB1 + (long)kt * ldb);
    };
    auto stage = [&](int buf) {
        As[buf][aK + 0][aRow] = a0.x;
        As[buf][aK + 1][aRow] = a0.y;
        As[buf][aK + 2][aRow] = a0.z;
        As[buf][aK + 3][aRow] = a0.w;
        As[buf][aK + 0][aRow + 64] = a1.x;
        As[buf][aK + 1][aRow + 64] = a1.y;
        As[buf][aK + 2][aRow + 64] = a1.z;
        As[buf][aK + 3][aRow + 64] = a1.w;
        *(float4*)&Bs[buf][bK][bCol]     = b0;
        *(float4*)&Bs[buf][bK + 8][bCol] = b1;
    };

    loadTile(0);
    stage(0);
    __syncthreads();

    // packed f32x2 accumulators: acc2[i][j] holds cols {2j, 2j+1} of row i
    unsigned long long acc2[8][4];
    #pragma unroll
    for (int i = 0; i < 8; ++i)
        #pragma unroll
        for (int j = 0; j < 4; ++j) acc2[i][j] = 0ull;

    #pragma unroll
    for (int t = 0; t < 8; ++t) {
        const int cur = t & 1;
        if (t < 7) loadTile((t + 1) * 16);

        #pragma unroll
        for (int kk = 0; kk < 16; ++kk) {
            float av[8];
            *(float4*)&av[0] = *(const float4*)&As[cur][kk][ty * 8];
            *(float4*)&av[4] = *(const float4*)&As[cur][kk][ty * 8 + 4];
            ulonglong2 q0 = *(const ulonglong2*)&Bs[cur][kk][tx * 8];
            ulonglong2 q1 = *(const ulonglong2*)&Bs[cur][kk][tx * 8 + 4];
            unsigned long long bv2[4] = {q0.x, q0.y, q1.x, q1.y};
            #pragma unroll
            for (int i = 0; i < 8; ++i) {
                unsigned long long aD;
                asm("mov.b64 %0, {%1, %1};" : "=l"(aD) : "r"(__float_as_uint(av[i])));
                #pragma unroll
                for (int j = 0; j < 4; ++j)
                    asm("fma.rn.f32x2 %0, %1, %2, %0;"
                        : "+l"(acc2[i][j]) : "l"(aD), "l"(bv2[j]));
            }
        }
        if (t < 7) {
            stage(cur ^ 1);
            __syncthreads();
        }
    }

    float bb[8] = {0.f, 0.f, 0.f, 0.f, 0.f, 0.f, 0.f, 0.f};
    if (bias) {
        #pragma unroll
        for (int j = 0; j < 8; ++j) bb[j] = bias[colBlock + tx * 8 + j];
    }

    const long mBase = rowBase + ty * 8;
    float* Cb = C + colOff + colBlock + tx * 8;
    #pragma unroll
    for (int i = 0; i < 8; ++i) {
        const long r = mBase + i;
        if (r < M) {
            float cv[8];
            #pragma unroll
            for (int j = 0; j < 4; ++j) {
                unsigned int lo, hi;
                asm("mov.b64 {%0, %1}, %2;" : "=r"(lo), "=r"(hi) : "l"(acc2[i][j]));
                cv[2 * j]     = __uint_as_float(lo) + bb[2 * j];
                cv[2 * j + 1] = __uint_as_float(hi) + bb[2 * j + 1];
            }
            *(float4*)(Cb + r * ldc)     = make_float4(cv[0], cv[1], cv[2], cv[3]);
            *(float4*)(Cb + r * ldc + 4) = make_float4(cv[4], cv[5], cv[6], cv[7]);
        }
    }
}

// ---------------------------------------------------------------------------
// Elementwise LSTM cell per level + fused output projection (warp per node).
// ---------------------------------------------------------------------------
__device__ __forceinline__ float sigm(float x) { return 1.0f / (1.0f + __expf(-x)); }

__global__ void __launch_bounds__(256)
node_update(const int n, const long s0, const int internal,
            const float* __restrict__ xall,
            const float* __restrict__ tiou,
            const float* __restrict__ tf,
            float* __restrict__ hbuf, float* __restrict__ cbuf,
            const float* __restrict__ Wout,
            const float* __restrict__ bout,
            float* __restrict__ out)
{
    __shared__ float sW[640];
    __shared__ float sB[5];
    const int tid = threadIdx.x;
    for (int i = tid; i < 640; i += 256) sW[i] = Wout[i];
    if (tid < 5) sB[tid] = bout[tid];
    __syncthreads();

    const int lane = tid & 31;
    const long j = (long)blockIdx.x * 8 + (tid >> 5);
    if (j >= n) return;
    const long g = s0 + j;
    const int k0 = lane * 4;

    const float* xr = xall + g * 512 + k0;
    float4 vi = *(const float4*)(xr);
    float4 vo = *(const float4*)(xr + 128);
    float4 vu = *(const float4*)(xr + 256);
    float4 fc = make_float4(0.f, 0.f, 0.f, 0.f);

    if (internal) {
        const float* ti = tiou + j * 384 + k0;
        float4 d0 = *(const float4*)(ti);
        float4 d1 = *(const float4*)(ti + 128);
        float4 d2 = *(const float4*)(ti + 256);
        vi.x += d0.x; vi.y += d0.y; vi.z += d0.z; vi.w += d0.w;
        vo.x += d1.x; vo.y += d1.y; vo.z += d1.z; vo.w += d1.w;
        vu.x += d2.x; vu.y += d2.y; vu.z += d2.z; vu.w += d2.w;

        float4 xf = *(const float4*)(xr + 384);
        const float* tl = tf + (j * 2) * 128 + k0;
        float4 fl = *(const float4*)(tl);
        float4 fr = *(const float4*)(tl + 128);
        const float* cl = cbuf + (2 * g + 1) * 128 + k0;
        float4 cL = *(const float4*)(cl);
        float4 cR = *(const float4*)(cl + 128);

        fc.x = sigm(xf.x + fl.x) * cL.x + sigm(xf.x + fr.x) * cR.x;
        fc.y = sigm(xf.y + fl.y) * cL.y + sigm(xf.y + fr.y) * cR.y;
        fc.z = sigm(xf.z + fl.z) * cL.z + sigm(xf.z + fr.z) * cR.z;
        fc.w = sigm(xf.w + fl.w) * cL.w + sigm(xf.w + fr.w) * cR.w;
    }

    float4 cc, hh;
    cc.x = sigm(vi.x) * tanhf(vu.x) + fc.x;
    cc.y = sigm(vi.y) * tanhf(vu.y) + fc.y;
    cc.z = sigm(vi.z) * tanhf(vu.z) + fc.z;
    cc.w = sigm(vi.w) * tanhf(vu.w) + fc.w;
    hh.x = sigm(vo.x) * tanhf(cc.x);
    hh.y = sigm(vo.y) * tanhf(cc.y);
    hh.z = sigm(vo.z) * tanhf(cc.z);
    hh.w = sigm(vo.w) * tanhf(cc.w);

    *(float4*)(cbuf + g * 128 + k0) = cc;
    *(float4*)(hbuf + g * 128 + k0) = hh;

    // fused output projection: out[g] = h[g] @ W_out + b_out
    const float* w = sW + k0 * 5;
    float a0 = hh.x * w[0]  + hh.y * w[5]  + hh.z * w[10] + hh.w * w[15];
    float a1 = hh.x * w[1]  + hh.y * w[6]  + hh.z * w[11] + hh.w * w[16];
    float a2 = hh.x * w[2]  + hh.y * w[7]  + hh.z * w[12] + hh.w * w[17];
    float a3 = hh.x * w[3]  + hh.y * w[8]  + hh.z * w[13] + hh.w * w[18];
    float a4 = hh.x * w[4]  + hh.y * w[9]  + hh.z * w[14] + hh.w * w[19];

    #pragma unroll
    for (int off = 16; off > 0; off >>= 1) {
        a0 += __shfl_down_sync(0xffffffffu, a0, off);
        a1 += __shfl_down_sync(0xffffffffu, a1, off);
        a2 += __shfl_down_sync(0xffffffffu, a2, off);
        a3 += __shfl_down_sync(0xffffffffu, a3, off);
        a4 += __shfl_down_sync(0xffffffffu, a4, off);
    }
    if (lane == 0) {
        float* op = out + g * 5;
        op[0] = a0 + sB[0];
        op[1] = a1 + sB[1];
        op[2] = a2 + sB[2];
        op[3] = a3 + sB[3];
        op[4] = a4 + sB[4];
    }
}

// ---------------------------------------------------------------------------
extern "C" void kernel_launch(void* const* d_in, const int* in_sizes, int n_in,
                              void* d_out, int out_size)
{
    const int*   x_ids = (const int*)  d_in[0];
    const int*   mask  = (const int*)  d_in[1];
    const float* emb   = (const float*)d_in[2];
    const float* W_iou = (const float*)d_in[3];
    const float* U_iou = (const float*)d_in[4];
    const float* b_iou = (const float*)d_in[5];
    const float* W_f   = (const float*)d_in[6];
    const float* U_f   = (const float*)d_in[7];
    const float* b_f   = (const float*)d_in[8];
    const float* W_out = (const float*)d_in[9];
    const float* b_out = (const float*)d_in[10];
    float* out = (float*)d_out;

    float *xall, *hb, *cb, *tiou, *tfb;
    cudaGetSymbolAddress((void**)&xall, g_xall);
    cudaGetSymbolAddress((void**)&hb,   g_h);
    cudaGetSymbolAddress((void**)&cb,   g_c);
    cudaGetSymbolAddress((void**)&tiou, g_tiou);
    cudaGetSymbolAddress((void**)&tfb,  g_tf);

    const int T = 256;
    const int MB = (NTOT + 127) / 128;   // 2048

    // Phase A: x_all = gather(emb) @ [W_iou | W_f] + [b_iou | b_f]
    gemm128<0><<<dim3(MB, 3), T>>>(NTOT, W_iou, 384, b_iou, xall, 512, 0,
                                   x_ids, mask, emb, nullptr, 0L);
    gemm128<0><<<dim3(MB, 1), T>>>(NTOT, W_f, 128, b_f, xall, 512, 384,
                                   x_ids, mask, emb, nullptr, 0L);

    // Leaf level: d = 17, n = 131072, s0 = 131071, fc = 0
    node_update<<<131072 / 8, T>>>(131072, 131071L, 0, xall, nullptr, nullptr,
                                   hb, cb, W_out, b_out, out);

    // Internal levels, bottom-up
    for (int d = 16; d >= 0; --d) {
        const int  n   = 1 << d;
        const long s0  = (long)n - 1;
        const long cs0 = 2L * n - 1;   // first child's global index

        gemm128<1><<<dim3((n + 127) / 128, 3), T>>>(
            n, U_iou, 384, nullptr, tiou, 384, 0,
            nullptr, nullptr, nullptr, hb, cs0);

        gemm128<2><<<dim3((2 * n + 127) / 128, 1), T>>>(
            2 * n, U_f, 128, nullptr, tfb, 128, 0,
            nullptr, nullptr, nullptr, hb, cs0);

        node_update<<<(n + 7) / 8, T>>>(n, s0, 1, xall, tiou, tfb,
                                        hb, cb, W_out, b_out, out);
    }
}